// round 12
// baseline (speedup 1.0000x reference)
#include <cuda_runtime.h>

#define NMAX 8192

// Scratch — zero-initialized at module load; reduce_kernel restores accumulator
// zeros after every call so graph replays see a clean state. g_contrib is
// overwritten every call, never cleaned.
__device__ int      g_cntpack[2][NMAX];   // low 16: cnt, high 16: pos_cnt
__device__ float    g_sumexp[2][NMAX];    // sum of exp(out[i]) over mask
__device__ float    g_poslog[2][NMAX];    // sum of out[i] over mask & pos
__device__ float    g_contrib[NMAX];      // per-column contribution (overwritten)
__device__ float    g_res;                // cross-block partial sum
__device__ unsigned g_done;               // block-completion counter

// Persistent-grid row-chunk scan. Each warp grid-strides over 256-quad chunks
// (a chunk never spans a row, so outs[i]/targets[i]/expf/pack stay warp-uniform
// per chunk). 740 resident blocks (5/SM x 148) eliminate wave-quantization idle
// that a 2048-block launch suffers (2.77 waves, 23%-empty tail wave).
// Inner body identical to the best-measured R8/R11 hit path.
__global__ void __launch_bounds__(256) main_kernel(
    const int4* __restrict__ adj,
    const float* __restrict__ outs,
    const int* __restrict__ tgt,
    int rowShift,                          // log2(quads per row)
    int totalChunks)                       // N*N/4/256
{
    const int lane       = threadIdx.x & 31;
    const int warpId     = (blockIdx.x * blockDim.x + threadIdx.x) >> 5;
    const int totalWarps = (gridDim.x * blockDim.x) >> 5;

    for (int chunk = warpId; chunk < totalChunks; chunk += totalWarps) {
        const long long quadBase = (long long)chunk << 8;           // 256 quads
        // Issue the 8 adjacency loads FIRST so they overlap the scalar loads.
        int4 vv[8];
        #pragma unroll
        for (int u = 0; u < 8; u++)
            vv[u] = __ldg(&adj[quadBase + u * 32 + lane]);

        const int i      = (int)(quadBase >> rowShift);             // row (uniform)
        const int cqBase = (int)(quadBase & ((1 << rowShift) - 1));

        const float o    = __ldg(&outs[i]);
        const int   p    = (__ldg(&tgt[i]) != 0) ? 1 : 0;
        const float e    = expf(o);
        const int   pack = 1 + (p << 16);

        #pragma unroll
        for (int u = 0; u < 8; u++) {
            int4 v = vv[u];
            if ((v.x | v.y | v.z | v.w) == 0) continue;             // ~98.5%

            int c = (cqBase + u * 32 + lane) << 2;                  // first column
            #pragma unroll
            for (int w = 0; w < 4; w++) {
                int val = (w == 0) ? v.x : (w == 1) ? v.y : (w == 2) ? v.z : v.w;
                int cc = c + w;
                if (val != 0 && cc != i) {
                    int side = (i < cc) ? 0 : 1;  // 0 = lower (i < k), 1 = upper
                    atomicAdd(&g_cntpack[side][cc], pack);
                    atomicAdd(&g_sumexp[side][cc], e);
                    if (p) atomicAdd(&g_poslog[side][cc], o);
                }
            }
        }
    }
}

// Per-column contribution: 6 independent loads, compute, overwrite g_contrib[c].
// No search, no clean, no reduction — single flat memory round-trip.
__global__ void __launch_bounds__(256) contrib_kernel(int N) {
    int c = blockIdx.x * blockDim.x + threadIdx.x;
    if (c >= N) return;

    int   pack0 = g_cntpack[0][c], pack1 = g_cntpack[1][c];
    float se0 = g_sumexp[0][c], se1 = g_sumexp[1][c];
    float pl0 = g_poslog[0][c], pl1 = g_poslog[1][c];

    int cnt0 = pack0 & 0xFFFF, pc0 = pack0 >> 16;
    int cnt1 = pack1 & 0xFFFF, pc1 = pack1 >> 16;

    float v = 0.f;
    if (cnt0 > 0 && pc0 == 1) v += (logf(se0) - pl0) / (float)cnt0;
    if (cnt1 > 0 && pc1 == 1) v += (logf(se1) - pl1) / (float)cnt1;
    g_contrib[c] = v;
}

// Gather g_contrib over idx entries — ONE gather per thread (duplicates in the
// sorted idx supply multiplicity for free), clean the accumulator arrays
// (disjoint from what we read), block-reduce, last block publishes out[0].
__global__ void __launch_bounds__(256) reduce_kernel(
    float* __restrict__ out,
    const int* __restrict__ idx,
    int N, int K)
{
    int t = blockIdx.x * blockDim.x + threadIdx.x;

    float local = 0.f;
    if (t < K) local = g_contrib[__ldg(&idx[t])];

    if (t < N) {   // self-clean accumulators for next replay (not g_contrib)
        g_cntpack[0][t] = 0; g_cntpack[1][t] = 0;
        g_sumexp[0][t] = 0.f; g_sumexp[1][t] = 0.f;
        g_poslog[0][t] = 0.f; g_poslog[1][t] = 0.f;
    }

    #pragma unroll
    for (int s = 16; s > 0; s >>= 1)
        local += __shfl_xor_sync(0xFFFFFFFF, local, s);

    __shared__ float warpsum[8];
    int lane = threadIdx.x & 31, wid = threadIdx.x >> 5;
    if (lane == 0) warpsum[wid] = local;
    __syncthreads();
    if (wid == 0) {
        float b = (lane < 8) ? warpsum[lane] : 0.f;
        #pragma unroll
        for (int s = 4; s > 0; s >>= 1)
            b += __shfl_xor_sync(0xFFFFFFFF, b, s);
        if (lane == 0) {
            atomicAdd(&g_res, b);
            __threadfence();
            unsigned d = atomicAdd(&g_done, 1u);
            if (d == gridDim.x - 1) {
                out[0] = atomicExch(&g_res, 0.f);
                g_done = 0;
            }
        }
    }
}

extern "C" void kernel_launch(void* const* d_in, const int* in_sizes, int n_in,
                              void* d_out, int out_size) {
    const float* outs = (const float*)d_in[0];   // outputs  [N] f32
    const int*   tgt  = (const int*)d_in[1];     // targets  [N] i32
    const int*   adj  = (const int*)d_in[2];     // node_adj [N,N] i32
    const int*   idx  = (const int*)d_in[3];     // idx_node [K] i32 (sorted)
    int N = in_sizes[0];
    int K = in_sizes[3];
    float* out = (float*)d_out;

    // quadsPerRow = N/4 is a power of two; rowShift = log2(N/4)
    int rowShift = 0;
    for (int t = N >> 2; t > 1; t >>= 1) rowShift++;

    long long totalQuads = ((long long)N * N) >> 2;
    int totalChunks = (int)(totalQuads >> 8);    // 256 quads per chunk

    // Persistent grid: 5 blocks/SM x 148 SMs. Grid-stride keeps every SM busy
    // until the last ~2% of chunks (no wave-quantization idle).
    main_kernel<<<740, 256>>>((const int4*)adj, outs, tgt, rowShift, totalChunks);
    contrib_kernel<<<(N + 255) / 256, 256>>>(N);
    reduce_kernel<<<(N + 255) / 256, 256>>>(out, idx, N, K);
}

// round 13
// speedup vs baseline: 1.0994x; 1.0994x over previous
#include <cuda_runtime.h>

#define NMAX 8192

// Scratch — zero-initialized at module load; reduce_kernel restores accumulator
// zeros after every call so graph replays see a clean state. g_contrib is
// overwritten every call, never cleaned.
__device__ int      g_cntpack[2][NMAX];   // low 16: cnt, high 16: pos_cnt
__device__ float    g_sumexp[2][NMAX];    // sum of exp(out[i]) over mask
__device__ float    g_poslog[2][NMAX];    // sum of out[i] over mask & pos
__device__ float    g_contrib[NMAX];      // per-column contribution (overwritten)
__device__ float    g_res;                // cross-block partial sum
__device__ unsigned g_done;               // block-completion counter

// Persistent-grid row-chunk scan, occupancy-fixed version of R12:
//  - __launch_bounds__(256, 5) guarantees all 740 blocks are resident (no waves)
//  - all-int32 index math in the hot loop (2^24 quads fits int) to cut regs
//  - chunk = 256 quads, row-aligned -> warp-uniform row scalars per chunk
//  - inner hit path identical to the best-measured R8/R11 code
__global__ void __launch_bounds__(256, 5) main_kernel(
    const int4* __restrict__ adj,
    const float* __restrict__ outs,
    const int* __restrict__ tgt,
    int rowShift,                          // log2(quads per row)
    int totalChunks)                       // N*N/4/256
{
    const int lane       = threadIdx.x & 31;
    const int warpId     = (blockIdx.x * blockDim.x + threadIdx.x) >> 5;
    const int totalWarps = (gridDim.x * blockDim.x) >> 5;
    const int rowMask    = (1 << rowShift) - 1;

    for (int chunk = warpId; chunk < totalChunks; chunk += totalWarps) {
        const int quadBase = chunk << 8;                        // 256 quads
        const int4* p = adj + quadBase + lane;                  // 64-bit addr once

        // Issue the 8 adjacency loads FIRST so they overlap the scalar loads.
        int4 vv[8];
        #pragma unroll
        for (int u = 0; u < 8; u++)
            vv[u] = __ldg(p + u * 32);

        const int i      = quadBase >> rowShift;                // row (uniform)
        const int cqBase = quadBase & rowMask;

        const float o    = __ldg(&outs[i]);
        const int   pos  = (__ldg(&tgt[i]) != 0) ? 1 : 0;
        const float e    = expf(o);
        const int   pack = 1 + (pos << 16);

        #pragma unroll
        for (int u = 0; u < 8; u++) {
            int4 v = vv[u];
            if ((v.x | v.y | v.z | v.w) == 0) continue;         // ~98.5%

            int c = (cqBase + u * 32 + lane) << 2;              // first column
            #pragma unroll
            for (int w = 0; w < 4; w++) {
                int val = (w == 0) ? v.x : (w == 1) ? v.y : (w == 2) ? v.z : v.w;
                int cc = c + w;
                if (val != 0 && cc != i) {
                    int side = (i < cc) ? 0 : 1;  // 0 = lower (i < k), 1 = upper
                    atomicAdd(&g_cntpack[side][cc], pack);
                    atomicAdd(&g_sumexp[side][cc], e);
                    if (pos) atomicAdd(&g_poslog[side][cc], o);
                }
            }
        }
    }
}

// Per-column contribution: 6 independent loads, compute, overwrite g_contrib[c].
// No search, no clean, no reduction — single flat memory round-trip.
__global__ void __launch_bounds__(256) contrib_kernel(int N) {
    int c = blockIdx.x * blockDim.x + threadIdx.x;
    if (c >= N) return;

    int   pack0 = g_cntpack[0][c], pack1 = g_cntpack[1][c];
    float se0 = g_sumexp[0][c], se1 = g_sumexp[1][c];
    float pl0 = g_poslog[0][c], pl1 = g_poslog[1][c];

    int cnt0 = pack0 & 0xFFFF, pc0 = pack0 >> 16;
    int cnt1 = pack1 & 0xFFFF, pc1 = pack1 >> 16;

    float v = 0.f;
    if (cnt0 > 0 && pc0 == 1) v += (logf(se0) - pl0) / (float)cnt0;
    if (cnt1 > 0 && pc1 == 1) v += (logf(se1) - pl1) / (float)cnt1;
    g_contrib[c] = v;
}

// Gather g_contrib over idx entries — ONE gather per thread (duplicates in the
// sorted idx supply multiplicity for free), clean the accumulator arrays
// (disjoint from what we read), block-reduce, last block publishes out[0].
__global__ void __launch_bounds__(256) reduce_kernel(
    float* __restrict__ out,
    const int* __restrict__ idx,
    int N, int K)
{
    int t = blockIdx.x * blockDim.x + threadIdx.x;

    float local = 0.f;
    if (t < K) local = g_contrib[__ldg(&idx[t])];

    if (t < N) {   // self-clean accumulators for next replay (not g_contrib)
        g_cntpack[0][t] = 0; g_cntpack[1][t] = 0;
        g_sumexp[0][t] = 0.f; g_sumexp[1][t] = 0.f;
        g_poslog[0][t] = 0.f; g_poslog[1][t] = 0.f;
    }

    #pragma unroll
    for (int s = 16; s > 0; s >>= 1)
        local += __shfl_xor_sync(0xFFFFFFFF, local, s);

    __shared__ float warpsum[8];
    int lane = threadIdx.x & 31, wid = threadIdx.x >> 5;
    if (lane == 0) warpsum[wid] = local;
    __syncthreads();
    if (wid == 0) {
        float b = (lane < 8) ? warpsum[lane] : 0.f;
        #pragma unroll
        for (int s = 4; s > 0; s >>= 1)
            b += __shfl_xor_sync(0xFFFFFFFF, b, s);
        if (lane == 0) {
            atomicAdd(&g_res, b);
            __threadfence();
            unsigned d = atomicAdd(&g_done, 1u);
            if (d == gridDim.x - 1) {
                out[0] = atomicExch(&g_res, 0.f);
                g_done = 0;
            }
        }
    }
}

extern "C" void kernel_launch(void* const* d_in, const int* in_sizes, int n_in,
                              void* d_out, int out_size) {
    const float* outs = (const float*)d_in[0];   // outputs  [N] f32
    const int*   tgt  = (const int*)d_in[1];     // targets  [N] i32
    const int*   adj  = (const int*)d_in[2];     // node_adj [N,N] i32
    const int*   idx  = (const int*)d_in[3];     // idx_node [K] i32 (sorted)
    int N = in_sizes[0];
    int K = in_sizes[3];
    float* out = (float*)d_out;

    // quadsPerRow = N/4 is a power of two; rowShift = log2(N/4)
    int rowShift = 0;
    for (int t = N >> 2; t > 1; t >>= 1) rowShift++;

    long long totalQuads = ((long long)N * N) >> 2;
    int totalChunks = (int)(totalQuads >> 8);    // 256 quads per chunk

    // Persistent grid: 5 blocks/SM x 148 SMs, all resident simultaneously.
    main_kernel<<<740, 256>>>((const int4*)adj, outs, tgt, rowShift, totalChunks);
    contrib_kernel<<<(N + 255) / 256, 256>>>(N);
    reduce_kernel<<<(N + 255) / 256, 256>>>(out, idx, N, K);
}